// round 7
// baseline (speedup 1.0000x reference)
#include <cuda_runtime.h>
#include <cuda_bf16.h>
#include <cstdint>

#define S_DIM 16
#define P_DIM 65536
#define N_DIM 256
#define K_DIM 32

// Warp-granular fused fill+scatter, 256-bit stores.
// Each warp owns a contiguous 2048-float range of one (channel,row):
// zeroes it with st.global.v8.f32 (32B/lane/instr, 1KB/warp-instr), then
// scatters the hot entries landing in its range. Cross-warp writes never
// alias -> __syncwarp() suffices.
//
// CTA = 8 warps = 16384 floats -> 4 CTAs per row; grid = 3*256*4 = 3072.
#define WARP_FLOATS 2048
#define CTA_FLOATS  (WARP_FLOATS * 8)       // 16384
#define V8_PER_LANE (WARP_FLOATS / 8 / 32)  // 8 st.global.v8 per lane

__device__ __forceinline__ void stg_zero_v8(float* p) {
    asm volatile(
        "st.global.v8.f32 [%0], {%1, %1, %1, %1, %1, %1, %1, %1};"
        :: "l"(p), "f"(0.0f) : "memory");
}

__global__ void __launch_bounds__(256)
fused_kernel(const float4* __restrict__ schema_params, // [S, P] float4
             const int* __restrict__ schema_ids,       // [N]
             const int* __restrict__ indices,          // [N, K]
             float* __restrict__ out)                  // [3, N, P]
{
    const int bid  = blockIdx.x;
    const int seg  = bid & 3;           // which 16384-float chunk of the row
    const int row  = bid >> 2;          // 0..767
    const int c    = row >> 8;          // channel 0..2
    const int n    = row & 255;         // row 0..255
    const int warp = threadIdx.x >> 5;
    const int lane = threadIdx.x & 31;

    const int range_lo = seg * CTA_FLOATS + warp * WARP_FLOATS;

    // Prefetch this lane's index; latency hides under the fill stores.
    const int p = __ldg(&indices[n * K_DIM + lane]);

    // ---- Phase 1: zero fill this warp's 2048 floats, 8x v8.f32 per lane ----
    float* wbase = out + (size_t)row * P_DIM + range_lo + lane * 8;
#pragma unroll
    for (int j = 0; j < V8_PER_LANE; j++) {
        stg_zero_v8(wbase + j * 256);   // 32 lanes * 8 floats = 256 floats/step
    }

    __syncwarp();   // order this warp's zeros before its scatter writes

    // ---- Phase 2: scatter hot entries landing in this warp's range ----
    const bool in_range = ((unsigned)(p - range_lo) < (unsigned)WARP_FLOATS);

    unsigned mask   = __match_any_sync(0xffffffffu, p);
    int      count  = __popc(mask);
    bool     leader = (lane == (__ffs(mask) - 1));

    if (leader && in_range) {
        const int sid = __ldg(&schema_ids[n]);
        float4 sp = __ldg(&schema_params[(size_t)sid * P_DIM + p]);
        // proj rows: c0 = f2+f3, c1 = f1, c2 = f3
        float v = (c == 0) ? (sp.z + sp.w) : (c == 1) ? sp.y : sp.w;
        float b = 1.0f - v;
        float r = b;
        for (int i = 1; i < count; i++) r *= b;
        out[(size_t)row * P_DIM + p] = 1.0f - r;
    }
}

extern "C" void kernel_launch(void* const* d_in, const int* in_sizes, int n_in,
                              void* d_out, int out_size) {
    const float4* schema_params = (const float4*)d_in[0];   // (16, 65536, 4) fp32
    const int*    schema_ids    = (const int*)d_in[1];      // (256,)
    const int*    indices       = (const int*)d_in[2];      // (256, 32)
    float*        out           = (float*)d_out;            // (3, 256, 65536) fp32

    const int blocks = 3 * N_DIM * (P_DIM / CTA_FLOATS);    // 3072
    fused_kernel<<<blocks, 256>>>(schema_params, schema_ids, indices, out);
}